// round 6
// baseline (speedup 1.0000x reference)
#include <cuda_runtime.h>
#include <cstdint>
#include <math_constants.h>

// Problem constants (shapes fixed by the dataset)
#define NCLS   64        // n
#define KSUP   5         // k
#define QPG    128       // q
#define DIM    256       // d
#define GROUP  (KSUP + QPG)   // 133
#define NQ     (NCLS * QPG)   // 8192
#define KNEIGH 10

// ---------------- scratch (device globals: allocation-free) ----------------
__device__ float g_qn[NQ * DIM];        // normalized queries      (8 MB)
__device__ float g_query[NQ * DIM];     // raw queries, contiguous (8 MB)
__device__ float g_proto[NCLS * DIM];
__device__ float g_pn[NCLS * DIM];      // normalized protos
__device__ float g_selfsim[NCLS];
__device__ float g_m[NCLS];
__device__ float g_preval[NQ];
__device__ int   g_prelabel[NQ];
__device__ float g_S[(size_t)NQ * NQ];  // query_sim (256 MB)
__device__ int   g_topidx[NQ * KNEIGH];
__device__ float g_ap[NCLS * DIM];      // adapted protos
__device__ float g_apn[NCLS * DIM];     // normalized adapted protos
__device__ float g_aq[NQ * DIM];        // adapted queries (8 MB)

// ---------------- helpers ----------------
__device__ __forceinline__ float block_reduce_sum_256(float v, float* sh8) {
    int t = threadIdx.x;
    #pragma unroll
    for (int o = 16; o > 0; o >>= 1) v += __shfl_down_sync(0xffffffffu, v, o);
    if ((t & 31) == 0) sh8[t >> 5] = v;
    __syncthreads();
    if (t < 8) {
        v = sh8[t];
        #pragma unroll
        for (int o = 4; o > 0; o >>= 1) v += __shfl_down_sync(0xffu, v, o);
        if (t == 0) sh8[0] = v;
    }
    __syncthreads();
    float r = sh8[0];
    __syncthreads();
    return r;
}

// ---------------- 1) prototypes: mean of support, normalize, self_sim ------
__global__ void proto_kernel(const float* __restrict__ x) {
    int b = blockIdx.x, t = threadIdx.x;
    __shared__ float sh8[8];
    float s = 0.f;
    #pragma unroll
    for (int i = 0; i < KSUP; i++)
        s += x[(size_t)(b * GROUP + i) * DIM + t];
    float p = s * (1.0f / KSUP);
    g_proto[b * DIM + t] = p;
    float ss = block_reduce_sum_256(p * p, sh8);
    float pn = p / sqrtf(ss);
    g_pn[b * DIM + t] = pn;
    float ss2 = block_reduce_sum_256(pn * pn, sh8);
    if (t == 0) g_selfsim[b] = ss2;
}

// ---------------- 2) queries: copy contiguous + normalize ------------------
__global__ void qnorm_kernel(const float* __restrict__ x) {
    int i = blockIdx.x, t = threadIdx.x;
    int g = i / QPG, qi = i - g * QPG;
    __shared__ float sh8[8];
    float v = x[(size_t)(g * GROUP + KSUP + qi) * DIM + t];
    g_query[(size_t)i * DIM + t] = v;
    float ss = block_reduce_sum_256(v * v, sh8);
    g_qn[(size_t)i * DIM + t] = v / sqrtf(ss);
}

// ---------------- 3) pre_sim + per-row argmax ------------------------------
__global__ void presim_kernel() {
    int i = blockIdx.x, t = threadIdx.x;
    __shared__ float q[DIM];
    __shared__ float sims[NCLS];
    q[t] = g_qn[(size_t)i * DIM + t];
    __syncthreads();
    int w = t >> 5, lane = t & 31;
    for (int c = w; c < NCLS; c += 8) {
        const float* p = g_pn + c * DIM;
        float s = 0.f;
        #pragma unroll
        for (int u = 0; u < DIM; u += 32) s += q[u + lane] * p[u + lane];
        #pragma unroll
        for (int o = 16; o > 0; o >>= 1) s += __shfl_down_sync(0xffffffffu, s, o);
        if (lane == 0) sims[c] = s;
    }
    __syncthreads();
    if (t == 0) {
        float best = -CUDART_INF_F; int bi = 0;
        #pragma unroll
        for (int c = 0; c < NCLS; c++)
            if (sims[c] > best) { best = sims[c]; bi = c; }
        g_preval[i] = best;
        g_prelabel[i] = bi;
    }
}

// ---------------- 4) per-class m = max(assigned sims, self_sim) ------------
__global__ void classmax_kernel() {
    int j = blockIdx.x, t = threadIdx.x;
    __shared__ float sh[256];
    float lm = -CUDART_INF_F;
    for (int i = t; i < NQ; i += 256)
        if (g_prelabel[i] == j) { float v = g_preval[i]; if (v > lm) lm = v; }
    sh[t] = lm;
    __syncthreads();
    for (int o = 128; o > 0; o >>= 1) {
        if (t < o) { if (sh[t + o] > sh[t]) sh[t] = sh[t + o]; }
        __syncthreads();
    }
    if (t == 0) {
        float m = sh[0];
        float ss = g_selfsim[j];
        g_m[j] = (ss > m) ? ss : m;
    }
}

// ---------------- 5) adapted prototypes ------------------------------------
__global__ void adaptproto_kernel() {
    int j = blockIdx.x, t = threadIdx.x;
    float m = g_m[j];
    float acc = 0.f, z = 0.f;
    for (int i = 0; i < NQ; i++) {
        if (g_prelabel[i] == j) {
            float w = expf(g_preval[i] - m);
            acc += w * g_query[(size_t)i * DIM + t];
            z += w;
        }
    }
    float es = expf(g_selfsim[j] - m);
    float Z = z + es;
    g_ap[j * DIM + t] = (acc + es * g_proto[j * DIM + t]) / Z;
}

// ---------------- 6) normalize adapted protos ------------------------------
__global__ void apnorm_kernel() {
    int j = blockIdx.x, t = threadIdx.x;
    __shared__ float sh8[8];
    float v = g_ap[j * DIM + t];
    float ss = block_reduce_sum_256(v * v, sh8);
    g_apn[j * DIM + t] = v / sqrtf(ss);
}

// ---------------- 7) S = Qn Qn^T  (symmetric, tiled SGEMM) -----------------
#define BM 128
#define BN 128
#define BK 16
__global__ __launch_bounds__(256) void simgemm_kernel() {
    int bx = blockIdx.x;  // col tile
    int by = blockIdx.y;  // row tile
    if (by > bx) return;  // upper triangle only; mirror-store below

    __shared__ float As[BK][BM];
    __shared__ float Bs[BK][BN];
    int tid = threadIdx.x;
    int tx = tid & 15, ty = tid >> 4;
    int rowBase = by * BM, colBase = bx * BN;

    float acc[8][8];
    #pragma unroll
    for (int i = 0; i < 8; i++)
        #pragma unroll
        for (int j = 0; j < 8; j++) acc[i][j] = 0.f;

    for (int kk = 0; kk < DIM; kk += BK) {
        #pragma unroll
        for (int l = 0; l < 2; l++) {
            int s = tid + l * 256;     // 0..511 float4 slots
            int r = s >> 2;            // 0..127
            int kc = (s & 3) * 4;      // 0,4,8,12
            float4 va = *(const float4*)&g_qn[(size_t)(rowBase + r) * DIM + kk + kc];
            As[kc + 0][r] = va.x; As[kc + 1][r] = va.y;
            As[kc + 2][r] = va.z; As[kc + 3][r] = va.w;
            float4 vb = *(const float4*)&g_qn[(size_t)(colBase + r) * DIM + kk + kc];
            Bs[kc + 0][r] = vb.x; Bs[kc + 1][r] = vb.y;
            Bs[kc + 2][r] = vb.z; Bs[kc + 3][r] = vb.w;
        }
        __syncthreads();
        #pragma unroll
        for (int k = 0; k < BK; k++) {
            float a[8], b[8];
            *(float4*)&a[0] = *(const float4*)&As[k][ty * 8];
            *(float4*)&a[4] = *(const float4*)&As[k][ty * 8 + 4];
            *(float4*)&b[0] = *(const float4*)&Bs[k][tx * 8];
            *(float4*)&b[4] = *(const float4*)&Bs[k][tx * 8 + 4];
            #pragma unroll
            for (int i = 0; i < 8; i++)
                #pragma unroll
                for (int j = 0; j < 8; j++)
                    acc[i][j] += a[i] * b[j];
        }
        __syncthreads();
    }

    // normal store
    #pragma unroll
    for (int i = 0; i < 8; i++) {
        size_t r = (size_t)(rowBase + ty * 8 + i);
        float4 v0 = make_float4(acc[i][0], acc[i][1], acc[i][2], acc[i][3]);
        float4 v1 = make_float4(acc[i][4], acc[i][5], acc[i][6], acc[i][7]);
        *(float4*)&g_S[r * NQ + colBase + tx * 8]     = v0;
        *(float4*)&g_S[r * NQ + colBase + tx * 8 + 4] = v1;
    }
    // mirrored (transposed) store
    if (bx != by) {
        #pragma unroll
        for (int j = 0; j < 8; j++) {
            size_t c = (size_t)(colBase + tx * 8 + j);
            float4 v0 = make_float4(acc[0][j], acc[1][j], acc[2][j], acc[3][j]);
            float4 v1 = make_float4(acc[4][j], acc[5][j], acc[6][j], acc[7][j]);
            *(float4*)&g_S[c * NQ + rowBase + ty * 8]     = v0;
            *(float4*)&g_S[c * NQ + rowBase + ty * 8 + 4] = v1;
        }
    }
}

// ---------------- 8) per-row top-10 ----------------------------------------
__global__ __launch_bounds__(256) void topk_kernel() {
    int i = blockIdx.x, t = threadIdx.x;
    const float* row = g_S + (size_t)i * NQ;

    float tv[KNEIGH]; int ti[KNEIGH];
    #pragma unroll
    for (int c = 0; c < KNEIGH; c++) { tv[c] = -CUDART_INF_F; ti[c] = -1; }

    for (int j = t; j < NQ; j += 256) {
        float s = row[j];
        if (s > tv[KNEIGH - 1]) {
            int jj = j;
            #pragma unroll
            for (int c = 0; c < KNEIGH; c++) {
                if (s > tv[c]) {
                    float pv = tv[c]; int pi = ti[c];
                    tv[c] = s; ti[c] = jj;
                    s = pv; jj = pi;
                }
            }
        }
    }

    __shared__ float cv[256][KNEIGH];
    __shared__ int   ci[256][KNEIGH];
    __shared__ float rv[256];
    __shared__ int   ri[256];
    __shared__ int   rt[256];
    #pragma unroll
    for (int c = 0; c < KNEIGH; c++) { cv[t][c] = tv[c]; ci[t][c] = ti[c]; }
    __syncthreads();

    int p = 0;
    for (int r = 0; r < KNEIGH; r++) {
        rv[t] = (p < KNEIGH) ? cv[t][p] : -CUDART_INF_F;
        ri[t] = (p < KNEIGH) ? ci[t][p] : -1;
        rt[t] = t;
        __syncthreads();
        for (int o = 128; o > 0; o >>= 1) {
            if (t < o) {
                if (rv[t + o] > rv[t]) {
                    rv[t] = rv[t + o]; ri[t] = ri[t + o]; rt[t] = rt[t + o];
                }
            }
            __syncthreads();
        }
        if (t == 0) g_topidx[i * KNEIGH + r] = ri[0];
        int win = rt[0];
        __syncthreads();
        if (t == win) p++;
    }
}

// ---------------- 9) mutual kNN softmax + adapted queries ------------------
__global__ void mutual_kernel() {
    int i = blockIdx.x, t = threadIdx.x;
    __shared__ int   nidx[KNEIGH];
    __shared__ float wgt[KNEIGH];
    if (t < KNEIGH) nidx[t] = g_topidx[i * KNEIGH + t];
    __syncthreads();
    if (t < KNEIGH) {
        int jn = nidx[t];
        bool mut = false;
        #pragma unroll
        for (int c = 0; c < KNEIGH; c++)
            if (g_topidx[jn * KNEIGH + c] == i) mut = true;
        wgt[t] = mut ? g_S[(size_t)i * NQ + jn] : -CUDART_INF_F;
    }
    __syncthreads();
    if (t == 0) {
        float m = -CUDART_INF_F;
        #pragma unroll
        for (int c = 0; c < KNEIGH; c++) if (wgt[c] > m) m = wgt[c];
        float sum = 0.f;
        float e[KNEIGH];
        #pragma unroll
        for (int c = 0; c < KNEIGH; c++) { e[c] = expf(wgt[c] - m); sum += e[c]; }
        float inv = 1.0f / sum;
        #pragma unroll
        for (int c = 0; c < KNEIGH; c++) wgt[c] = e[c] * inv;
    }
    __syncthreads();
    float acc = 0.f;
    #pragma unroll
    for (int c = 0; c < KNEIGH; c++) {
        float w = wgt[c];
        if (w != 0.f) acc += w * g_query[(size_t)nidx[c] * DIM + t];
    }
    g_aq[(size_t)i * DIM + t] = acc;
}

// ---------------- 10) final: tao * cos(adapted_query, adapted_proto) -------
__global__ void final_kernel(const float* __restrict__ tao, float* __restrict__ out) {
    int i = blockIdx.x, t = threadIdx.x;
    __shared__ float sh8[8];
    __shared__ float q[DIM];
    float v = g_aq[(size_t)i * DIM + t];
    float ss = block_reduce_sum_256(v * v, sh8);
    q[t] = v / sqrtf(ss);
    __syncthreads();
    int w = t >> 5, lane = t & 31;
    float tv = tao[0];
    for (int c = w; c < NCLS; c += 8) {
        const float* p = g_apn + c * DIM;
        float s = 0.f;
        #pragma unroll
        for (int u = 0; u < DIM; u += 32) s += q[u + lane] * p[u + lane];
        #pragma unroll
        for (int o = 16; o > 0; o >>= 1) s += __shfl_down_sync(0xffffffffu, s, o);
        if (lane == 0) out[(size_t)i * NCLS + c] = tv * s;
    }
}

// ---------------- launch ----------------------------------------------------
extern "C" void kernel_launch(void* const* d_in, const int* in_sizes, int n_in,
                              void* d_out, int out_size) {
    const float* x   = (const float*)d_in[0];
    const float* tao = (const float*)d_in[1];
    float* out = (float*)d_out;

    proto_kernel<<<NCLS, 256>>>(x);
    qnorm_kernel<<<NQ, 256>>>(x);
    presim_kernel<<<NQ, 256>>>();
    classmax_kernel<<<NCLS, 256>>>();
    adaptproto_kernel<<<NCLS, 256>>>();
    apnorm_kernel<<<NCLS, 256>>>();
    simgemm_kernel<<<dim3(NQ / BN, NQ / BM), 256>>>();
    topk_kernel<<<NQ, 256>>>();
    mutual_kernel<<<NQ, 256>>>();
    final_kernel<<<NQ, 256>>>(tao, out);
}